// round 16
// baseline (speedup 1.0000x reference)
#include <cuda_runtime.h>
#include <cuda_pipeline.h>

// Problem constants
#define S_GRID 14
#define NCLS   20
#define N_IMG  4096
#define CELLS  (N_IMG * S_GRID * S_GRID)   // 802816
#define PRED_C 30
#define TPB    128
#define NBLK   (CELLS / TPB)               // 6272 (exact)

// Persistent accumulators. Zero at module load; finalize kernel resets them
// after reading, so every graph replay starts clean.
__device__ double g_acc[4];    // [0]=cls, [1]=noobj, [2]=containing, [3]=reg

__global__ void __launch_bounds__(TPB) yolo_main_kernel(
    const float* __restrict__ pred,   // [CELLS, 30]
    const float* __restrict__ tbox,   // [CELLS, 4]
    const float* __restrict__ tcls,   // [CELLS, 20]
    const int*   __restrict__ mask)   // [CELLS]
{
    // Whole tile staged via cp.async: in-flight bytes decoupled from registers
    // and warp count. 27.5 KB/block, 8 blocks/SM co-resident.
    __shared__ __align__(16) float sp[TPB * PRED_C];  // 15360 B
    __shared__ __align__(16) float sc[TPB * NCLS];    // 10240 B
    __shared__ __align__(16) float stb[TPB * 4];      //  2048 B
    __shared__ __align__(16) int   smk[TPB];          //   512 B

    const int t    = threadIdx.x;
    const int base = blockIdx.x * TPB;

    // ---- issue ALL async copies (flat, 16B-aligned, fully coalesced) ----
    {
        const float4* g = reinterpret_cast<const float4*>(pred + (size_t)base * PRED_C);
        float4*       s = reinterpret_cast<float4*>(sp);
        #pragma unroll
        for (int idx = 0; idx < (TPB * PRED_C) / 4; idx += TPB)
            __pipeline_memcpy_async(&s[idx + t], &g[idx + t], 16);
        // (TPB*PRED_C)/4 = 960 = 7.5*TPB -> handle remainder
        if (t < ((TPB * PRED_C) / 4) % TPB)
            __pipeline_memcpy_async(&s[((TPB * PRED_C) / 4 / TPB) * TPB + t],
                                    &g[((TPB * PRED_C) / 4 / TPB) * TPB + t], 16);
    }
    {
        const float4* g = reinterpret_cast<const float4*>(tcls + (size_t)base * NCLS);
        float4*       s = reinterpret_cast<float4*>(sc);
        #pragma unroll
        for (int idx = 0; idx < (TPB * NCLS) / 4; idx += TPB)
            __pipeline_memcpy_async(&s[idx + t], &g[idx + t], 16);
    }
    {
        const float4* g = reinterpret_cast<const float4*>(tbox + (size_t)base * 4);
        float4*       s = reinterpret_cast<float4*>(stb);
        __pipeline_memcpy_async(&s[t], &g[t], 16);   // 128 float4s = TPB
    }
    {
        const float4* g = reinterpret_cast<const float4*>(mask + (size_t)base);
        float4*       s = reinterpret_cast<float4*>(smk);
        if (t < TPB / 4)
            __pipeline_memcpy_async(&s[t], &g[t], 16);
    }
    __pipeline_commit();
    __pipeline_wait_prior(0);
    __syncthreads();

    // ---- per-cell reads from smem (all conflict-free strides) ----
    const float* pr = sp + t * PRED_C;   // stride 30 words, LDS.64
    const float* tc = sc + t * NCLS;     // stride 20 words, LDS.128
    const float4 tb = reinterpret_cast<const float4*>(stb)[t];  // stride 4 words
    const float  m  = (smk[t] != 0) ? 1.0f : 0.0f;

    // ---- class loss: m * sum (pred_cls - target_cls)^2 ----
    float s = 0.f;
    #pragma unroll
    for (int j = 0; j < NCLS / 4; j++) {
        const float4 c = reinterpret_cast<const float4*>(tc)[j];
        const float q0 = pr[10 + 4 * j + 0] - c.x;
        const float q1 = pr[10 + 4 * j + 1] - c.y;
        const float q2 = pr[10 + 4 * j + 2] - c.z;
        const float q3 = pr[10 + 4 * j + 3] - c.w;
        s += q0 * q0 + q1 * q1 + q2 * q2 + q3 * q3;
    }
    float cls_s = m * s;

    // ---- no-object loss: (1-m) * sum_b conf_b^2 ----
    const float c0 = pr[4], c1 = pr[9];
    float noobj_s = (1.0f - m) * (c0 * c0 + c1 * c1);

    // ---- IoU per box (B=2) ----
    float iou[2];
    #pragma unroll
    for (int b = 0; b < 2; b++) {
        const float x = pr[5 * b + 0] * (1.0f / S_GRID);
        const float y = pr[5 * b + 1] * (1.0f / S_GRID);
        const float w = pr[5 * b + 2];
        const float h = pr[5 * b + 3];
        const float p1x = x - w * 0.5f, p1y = y - h * 0.5f;
        const float p2x = x + w * 0.5f, p2y = y + h * 0.5f;
        const float ltx = fmaxf(p1x, tb.x), lty = fmaxf(p1y, tb.y);
        const float rbx = fminf(p2x, tb.z), rby = fminf(p2y, tb.w);
        const float iw = fmaxf(rbx - ltx, 0.0f);
        const float ih = fmaxf(rby - lty, 0.0f);
        const float inter  = iw * ih;
        const float area_p = w * h;
        const float area_t = (tb.z - tb.x) * (tb.w - tb.y);
        iou[b] = inter / (area_p + area_t - inter);
    }

    // argmax over B=2 (first occurrence of max, like jnp.argmax)
    const bool pick1 = (iou[1] > iou[0]);
    const float bx = pick1 ? pr[5] : pr[0];
    const float by = pick1 ? pr[6] : pr[1];
    const float bw = pick1 ? pr[7] : pr[2];
    const float bh = pick1 ? pr[8] : pr[3];
    const float bc = pick1 ? pr[9] : pr[4];

    // ---- containing-object loss ----
    float cont_s = m * (bc - 1.0f) * (bc - 1.0f);

    // ---- regression loss (center + dim) ----
    const float dx = bx - tb.x;
    const float dy = by - tb.y;
    const float dw = sqrtf(bw) - sqrtf(tb.z);
    const float dh = sqrtf(bh) - sqrtf(tb.w);
    float reg_s = m * (dx * dx + dy * dy + dw * dw + dh * dh);

    // ---- reduction: warp shuffle, then across 4 warps ----
    #pragma unroll
    for (int off = 16; off > 0; off >>= 1) {
        cls_s   += __shfl_down_sync(0xFFFFFFFFu, cls_s,   off);
        noobj_s += __shfl_down_sync(0xFFFFFFFFu, noobj_s, off);
        cont_s  += __shfl_down_sync(0xFFFFFFFFu, cont_s,  off);
        reg_s   += __shfl_down_sync(0xFFFFFFFFu, reg_s,   off);
    }

    __shared__ float sh[4][4];  // 128 threads -> 4 warps
    const int wid = t >> 5;
    const int lid = t & 31;
    if (lid == 0) {
        sh[0][wid] = cls_s;
        sh[1][wid] = noobj_s;
        sh[2][wid] = cont_s;
        sh[3][wid] = reg_s;
    }
    __syncthreads();

    if (t == 0) {
        const float v0 = sh[0][0] + sh[0][1] + sh[0][2] + sh[0][3];
        const float v1 = sh[1][0] + sh[1][1] + sh[1][2] + sh[1][3];
        const float v2 = sh[2][0] + sh[2][1] + sh[2][2] + sh[2][3];
        const float v3 = sh[3][0] + sh[3][1] + sh[3][2] + sh[3][3];
        // Fire-and-forget REDs: block retires without an L2 round trip.
        atomicAdd(&g_acc[0], (double)v0);
        atomicAdd(&g_acc[1], (double)v1);
        atomicAdd(&g_acc[2], (double)v2);
        atomicAdd(&g_acc[3], (double)v3);
    }
}

__global__ void yolo_finalize_kernel(float* __restrict__ out) {
    // Runs after the main kernel (graph edge = device-wide ordering).
    const double cls_t   = g_acc[0];
    const double noobj_t = g_acc[1];
    const double cont_t  = g_acc[2];
    const double reg_t   = g_acc[3];
    const double inv_n = 1.0 / (double)N_IMG;
    const double cls   = cls_t   * inv_n;
    const double noobj = noobj_t * inv_n;
    const double cont  = cont_t  * inv_n;
    const double reg   = reg_t   * inv_n;
    out[0] = (float)(cls + 0.5 * noobj + 5.0 * reg + cont);
    out[1] = (float)reg;
    out[2] = (float)cont;
    out[3] = (float)noobj;
    out[4] = (float)cls;
    // Reset for the next graph replay.
    g_acc[0] = 0.0; g_acc[1] = 0.0; g_acc[2] = 0.0; g_acc[3] = 0.0;
}

extern "C" void kernel_launch(void* const* d_in, const int* in_sizes, int n_in,
                              void* d_out, int out_size) {
    // Identify inputs by element count (robust to ordering):
    //   pred: 24,084,480   tbox: 3,211,264   tcls: 16,056,320   mask: 802,816
    const float* pred = nullptr;
    const float* tbox = nullptr;
    const float* tcls = nullptr;
    const int*   msk  = nullptr;
    for (int k = 0; k < n_in; k++) {
        const long long sz = in_sizes[k];
        if      (sz == (long long)CELLS * PRED_C) pred = (const float*)d_in[k];
        else if (sz == (long long)CELLS * 4)      tbox = (const float*)d_in[k];
        else if (sz == (long long)CELLS * NCLS)   tcls = (const float*)d_in[k];
        else if (sz == (long long)CELLS)          msk  = (const int*)d_in[k];
    }
    float* out = (float*)d_out;

    yolo_main_kernel<<<NBLK, TPB>>>(pred, tbox, tcls, msk);
    yolo_finalize_kernel<<<1, 1>>>(out);
}

// round 17
// speedup vs baseline: 1.2731x; 1.2731x over previous
#include <cuda_runtime.h>

// Problem constants
#define S_GRID 14
#define NCLS   20
#define N_IMG  4096
#define CELLS  (N_IMG * S_GRID * S_GRID)   // 802816
#define PRED_C 30
#define TPB    256
#define NBLK   (CELLS / TPB)               // 3136 (exact)

// Persistent accumulators. Zero at module load; finalize kernel resets them
// after reading, so every graph replay starts clean.
__device__ double g_acc[4];    // [0]=cls, [1]=noobj, [2]=containing, [3]=reg

__global__ void __launch_bounds__(TPB) yolo_main_kernel(
    const float* __restrict__ pred,   // [CELLS, 30]
    const float* __restrict__ tbox,   // [CELLS, 4]
    const float* __restrict__ tcls,   // [CELLS, 20]
    const int*   __restrict__ mask)   // [CELLS]
{
    const int i = blockIdx.x * TPB + threadIdx.x;

    float cls_s = 0.f, noobj_s = 0.f, cont_s = 0.f, reg_s = 0.f;

    const float* prow = pred + (size_t)i * PRED_C;
    const int mraw = mask[i];

    if (mraw != 0) {
        // ======== object cell: needs full pred row + tbox + tcls ========
        float p[PRED_C];
        {
            const float2* p2 = reinterpret_cast<const float2*>(prow);
            #pragma unroll
            for (int j = 0; j < PRED_C / 2; j++) {
                const float2 v = p2[j];
                p[2 * j]     = v.x;
                p[2 * j + 1] = v.y;
            }
        }
        const float4 tb = reinterpret_cast<const float4*>(tbox)[i];

        // class loss (m=1)
        {
            const float4* tc4 = reinterpret_cast<const float4*>(tcls + (size_t)i * NCLS);
            float s = 0.f;
            #pragma unroll
            for (int j = 0; j < NCLS / 4; j++) {
                const float4 c = tc4[j];
                const float q0 = p[10 + 4 * j + 0] - c.x;
                const float q1 = p[10 + 4 * j + 1] - c.y;
                const float q2 = p[10 + 4 * j + 2] - c.z;
                const float q3 = p[10 + 4 * j + 3] - c.w;
                s += q0 * q0 + q1 * q1 + q2 * q2 + q3 * q3;
            }
            cls_s = s;
        }

        // IoU per box (B=2)
        float iou[2];
        #pragma unroll
        for (int b = 0; b < 2; b++) {
            const float x = p[5 * b + 0] * (1.0f / S_GRID);
            const float y = p[5 * b + 1] * (1.0f / S_GRID);
            const float w = p[5 * b + 2];
            const float h = p[5 * b + 3];
            const float p1x = x - w * 0.5f, p1y = y - h * 0.5f;
            const float p2x = x + w * 0.5f, p2y = y + h * 0.5f;
            const float ltx = fmaxf(p1x, tb.x), lty = fmaxf(p1y, tb.y);
            const float rbx = fminf(p2x, tb.z), rby = fminf(p2y, tb.w);
            const float iw = fmaxf(rbx - ltx, 0.0f);
            const float ih = fmaxf(rby - lty, 0.0f);
            const float inter  = iw * ih;
            const float area_p = w * h;
            const float area_t = (tb.z - tb.x) * (tb.w - tb.y);
            iou[b] = inter / (area_p + area_t - inter);
        }

        // argmax over B=2 (first occurrence of max, like jnp.argmax)
        const bool pick1 = (iou[1] > iou[0]);
        const float bx = pick1 ? p[5] : p[0];
        const float by = pick1 ? p[6] : p[1];
        const float bw = pick1 ? p[7] : p[2];
        const float bh = pick1 ? p[8] : p[3];
        const float bc = pick1 ? p[9] : p[4];

        cont_s = (bc - 1.0f) * (bc - 1.0f);

        const float dx = bx - tb.x;
        const float dy = by - tb.y;
        const float dw = sqrtf(bw) - sqrtf(tb.z);
        const float dh = sqrtf(bh) - sqrtf(tb.w);
        reg_s = dx * dx + dy * dy + dw * dw + dh * dh;
    } else {
        // ======== empty cell: only the two confidences are needed ========
        const float c0 = prow[4];
        const float c1 = prow[9];
        noobj_s = c0 * c0 + c1 * c1;
    }

    // ---- reduction: warp shuffle, then across 8 warps ----
    #pragma unroll
    for (int off = 16; off > 0; off >>= 1) {
        cls_s   += __shfl_down_sync(0xFFFFFFFFu, cls_s,   off);
        noobj_s += __shfl_down_sync(0xFFFFFFFFu, noobj_s, off);
        cont_s  += __shfl_down_sync(0xFFFFFFFFu, cont_s,  off);
        reg_s   += __shfl_down_sync(0xFFFFFFFFu, reg_s,   off);
    }

    __shared__ float sh[4][8];  // 256 threads -> 8 warps
    const int wid = threadIdx.x >> 5;
    const int lid = threadIdx.x & 31;
    if (lid == 0) {
        sh[0][wid] = cls_s;
        sh[1][wid] = noobj_s;
        sh[2][wid] = cont_s;
        sh[3][wid] = reg_s;
    }
    __syncthreads();

    if (wid == 0) {
        float v0 = (lid < 8) ? sh[0][lid] : 0.f;
        float v1 = (lid < 8) ? sh[1][lid] : 0.f;
        float v2 = (lid < 8) ? sh[2][lid] : 0.f;
        float v3 = (lid < 8) ? sh[3][lid] : 0.f;
        #pragma unroll
        for (int off = 4; off > 0; off >>= 1) {
            v0 += __shfl_down_sync(0xFFFFFFFFu, v0, off);
            v1 += __shfl_down_sync(0xFFFFFFFFu, v1, off);
            v2 += __shfl_down_sync(0xFFFFFFFFu, v2, off);
            v3 += __shfl_down_sync(0xFFFFFFFFu, v3, off);
        }
        if (lid == 0) {
            // Fire-and-forget REDs: block retires without an L2 round trip.
            atomicAdd(&g_acc[0], (double)v0);
            atomicAdd(&g_acc[1], (double)v1);
            atomicAdd(&g_acc[2], (double)v2);
            atomicAdd(&g_acc[3], (double)v3);
        }
    }
}

__global__ void yolo_finalize_kernel(float* __restrict__ out) {
    // Runs after the main kernel (graph edge = device-wide ordering).
    const double cls_t   = g_acc[0];
    const double noobj_t = g_acc[1];
    const double cont_t  = g_acc[2];
    const double reg_t   = g_acc[3];
    const double inv_n = 1.0 / (double)N_IMG;
    const double cls   = cls_t   * inv_n;
    const double noobj = noobj_t * inv_n;
    const double cont  = cont_t  * inv_n;
    const double reg   = reg_t   * inv_n;
    out[0] = (float)(cls + 0.5 * noobj + 5.0 * reg + cont);
    out[1] = (float)reg;
    out[2] = (float)cont;
    out[3] = (float)noobj;
    out[4] = (float)cls;
    // Reset for the next graph replay.
    g_acc[0] = 0.0; g_acc[1] = 0.0; g_acc[2] = 0.0; g_acc[3] = 0.0;
}

extern "C" void kernel_launch(void* const* d_in, const int* in_sizes, int n_in,
                              void* d_out, int out_size) {
    // Identify inputs by element count (robust to ordering):
    //   pred: 24,084,480   tbox: 3,211,264   tcls: 16,056,320   mask: 802,816
    const float* pred = nullptr;
    const float* tbox = nullptr;
    const float* tcls = nullptr;
    const int*   msk  = nullptr;
    for (int k = 0; k < n_in; k++) {
        const long long sz = in_sizes[k];
        if      (sz == (long long)CELLS * PRED_C) pred = (const float*)d_in[k];
        else if (sz == (long long)CELLS * 4)      tbox = (const float*)d_in[k];
        else if (sz == (long long)CELLS * NCLS)   tcls = (const float*)d_in[k];
        else if (sz == (long long)CELLS)          msk  = (const int*)d_in[k];
    }
    float* out = (float*)d_out;

    yolo_main_kernel<<<NBLK, TPB>>>(pred, tbox, tcls, msk);
    yolo_finalize_kernel<<<1, 1>>>(out);
}